// round 10
// baseline (speedup 1.0000x reference)
#include <cuda_runtime.h>
#include <cuda_fp16.h>
#include <math.h>
#include <stdint.h>

#define Bb 2
#define Tt 4096
#define Cc 768
#define NHh 12
#define HSs 64
#define BT (Bb*Tt)
#define C3 (3*Cc)

__device__ __half g_qkv[(size_t)BT * C3];   // [B*T, 3C] fp16
__device__ __half g_att[(size_t)BT * Cc];   // [B*T, C]  fp16
__device__ __half g_xh [(size_t)BT * Cc];   // x in fp16
__device__ __half g_wa [(size_t)Cc * C3];   // w_attn fp16
__device__ __half g_wp [(size_t)Cc * Cc];   // w_proj fp16

__device__ __forceinline__ uint32_t h2u(__half2 h) {
    return *reinterpret_cast<uint32_t*>(&h);
}
__device__ __forceinline__ uint32_t pk(float a, float b) {
    __half2 h = __floats2half2_rn(a, b);
    return h2u(h);
}
__device__ __forceinline__ float ex2(float x) {
    float r;
    asm("ex2.approx.ftz.f32 %0, %1;" : "=f"(r) : "f"(x));
    return r;
}
__device__ __forceinline__ uint32_t ex2h2(uint32_t x) {
    uint32_t r;
    asm("ex2.approx.f16x2 %0, %1;" : "=r"(r) : "r"(x));
    return r;
}
__device__ __forceinline__ void cp16(uint32_t dst, const void* src) {
    asm volatile("cp.async.cg.shared.global [%0], [%1], 16;" :: "r"(dst), "l"(src));
}
__device__ __forceinline__ void cp_commit() { asm volatile("cp.async.commit_group;"); }
__device__ __forceinline__ void cp_wait1()  { asm volatile("cp.async.wait_group 1;"); }
__device__ __forceinline__ void cp_wait0()  { asm volatile("cp.async.wait_group 0;"); }

__device__ __forceinline__ void mma_f16(float c[4], const uint32_t a[4], const uint32_t b[2]) {
    asm volatile(
        "mma.sync.aligned.m16n8k16.row.col.f32.f16.f16.f32 "
        "{%0,%1,%2,%3},{%4,%5,%6,%7},{%8,%9},{%0,%1,%2,%3};"
        : "+f"(c[0]), "+f"(c[1]), "+f"(c[2]), "+f"(c[3])
        : "r"(a[0]), "r"(a[1]), "r"(a[2]), "r"(a[3]), "r"(b[0]), "r"(b[1]));
}
__device__ __forceinline__ void ldsm4(uint32_t r[4], uint32_t saddr) {
    asm volatile("ldmatrix.sync.aligned.m8n8.x4.shared.b16 {%0,%1,%2,%3}, [%4];"
                 : "=r"(r[0]), "=r"(r[1]), "=r"(r[2]), "=r"(r[3]) : "r"(saddr));
}
__device__ __forceinline__ void ldsm4t(uint32_t r[4], uint32_t saddr) {
    asm volatile("ldmatrix.sync.aligned.m8n8.x4.trans.shared.b16 {%0,%1,%2,%3}, [%4];"
                 : "=r"(r[0]), "=r"(r[1]), "=r"(r[2]), "=r"(r[3]) : "r"(saddr));
}
__device__ __forceinline__ uint32_t cvs(const void* p) {
    return (uint32_t)__cvta_generic_to_shared(p);
}

// ---------------------------------------------------------------------------
// fp32 -> fp16 bulk convert
// ---------------------------------------------------------------------------
__global__ void f2h(const float* __restrict__ src, __half* __restrict__ dst, int n4)
{
    int i = blockIdx.x * blockDim.x + threadIdx.x;
    if (i < n4) {
        float4 v = *(const float4*)(src + (size_t)i * 4);
        uint2 u;
        u.x = pk(v.x, v.y);
        u.y = pk(v.z, v.w);
        *(uint2*)(dst + (size_t)i * 4) = u;
    }
}

// ---------------------------------------------------------------------------
// All-half GEMM (R9, verbatim): CTA 128x256, 8 warps, warp 64x64, kc=32,
// cp.async double-buffered, LDSM+HMMA hot loop.
// ---------------------------------------------------------------------------
#define LDAH 40
#define LDBH 264
#define GA_H(s) ((s) * 128 * LDAH)
#define GB_H(s) (2 * 128 * LDAH + (s) * 32 * LDBH)
#define GEMM_SMEM_H (2 * 128 * LDAH + 2 * 32 * LDBH)

template <typename TC>
__global__ __launch_bounds__(256)
void gemm_h16(const __half* __restrict__ A, const __half* __restrict__ B,
              TC* __restrict__ C, int M, int N, int K)
{
    extern __shared__ __half smh[];

    const int tid = threadIdx.x;
    const int lane = tid & 31, wid = tid >> 5;
    const int warpM = wid >> 2, warpN = wid & 3;
    const int lr = lane >> 2, lc = lane & 3;
    const int brow = blockIdx.y << 7, bcol = blockIdx.x << 8;

    const __half* Ab = A + (size_t)brow * K;
    const __half* Bbp = B + bcol;

    float acc[4][8][4];
    #pragma unroll
    for (int i = 0; i < 4; i++)
        #pragma unroll
        for (int j = 0; j < 8; j++)
            #pragma unroll
            for (int q = 0; q < 4; q++) acc[i][j][q] = 0.f;

    #define ISSUE(kt, s) do { \
        uint32_t as_ = cvs(smh + GA_H(s)); \
        uint32_t bs_ = cvs(smh + GB_H(s)); \
        _Pragma("unroll") \
        for (int it = 0; it < 2; it++) { \
            int idx = tid + it * 256; \
            int r = idx >> 2, c8 = (idx & 3) << 3; \
            cp16(as_ + (uint32_t)(r * LDAH + c8) * 2u, \
                 Ab + (size_t)r * K + (kt) * 32 + c8); \
        } \
        _Pragma("unroll") \
        for (int it = 0; it < 4; it++) { \
            int idx = tid + it * 256; \
            int r = idx >> 5, c8 = (idx & 31) << 3; \
            cp16(bs_ + (uint32_t)(r * LDBH + c8) * 2u, \
                 Bbp + (size_t)((kt) * 32 + r) * N + c8); \
        } \
        cp_commit(); \
    } while (0)

    const int NT = K >> 5;
    ISSUE(0, 0);

    const int aRow = lane & 15, aKoff = (lane & 16) ? 8 : 0;
    const int bRow = (lane & 7) + ((lane & 8) ? 8 : 0);
    const int bNoff = (lane & 16) ? 8 : 0;

    for (int kt = 0; kt < NT; kt++) {
        const int cur = kt & 1;
        if (kt + 1 < NT) { ISSUE(kt + 1, (kt + 1) & 1); cp_wait1(); }
        else cp_wait0();
        __syncthreads();

        const __half* Ac = smh + GA_H(cur);
        const __half* Bc = smh + GB_H(cur);
        #pragma unroll
        for (int ks = 0; ks < 2; ks++) {
            uint32_t af[4][4];
            #pragma unroll
            for (int mt = 0; mt < 4; mt++)
                ldsm4(af[mt], cvs(Ac + (warpM * 64 + mt * 16 + aRow) * LDAH
                                     + ks * 16 + aKoff));
            uint32_t bf[8][2];
            #pragma unroll
            for (int j2 = 0; j2 < 4; j2++) {
                uint32_t t[4];
                ldsm4t(t, cvs(Bc + (ks * 16 + bRow) * LDBH
                                 + warpN * 64 + j2 * 16 + bNoff));
                bf[2 * j2][0] = t[0]; bf[2 * j2][1] = t[1];
                bf[2 * j2 + 1][0] = t[2]; bf[2 * j2 + 1][1] = t[3];
            }
            #pragma unroll
            for (int mt = 0; mt < 4; mt++)
                #pragma unroll
                for (int nt = 0; nt < 8; nt++)
                    mma_f16(acc[mt][nt], af[mt], bf[nt]);
        }
        __syncthreads();
    }

    #pragma unroll
    for (int mt = 0; mt < 4; mt++)
        #pragma unroll
        for (int nt = 0; nt < 8; nt++) {
            int row = brow + warpM * 64 + mt * 16 + lr;
            int col = bcol + warpN * 64 + nt * 8 + 2 * lc;
            if constexpr (sizeof(TC) == 2) {
                *(__half2*)&C[(size_t)row * N + col] =
                    __floats2half2_rn(acc[mt][nt][0], acc[mt][nt][1]);
                *(__half2*)&C[(size_t)(row + 8) * N + col] =
                    __floats2half2_rn(acc[mt][nt][2], acc[mt][nt][3]);
            } else {
                *(float2*)&C[(size_t)row * N + col] =
                    make_float2(acc[mt][nt][0], acc[mt][nt][1]);
                *(float2*)&C[(size_t)(row + 8) * N + col] =
                    make_float2(acc[mt][nt][2], acc[mt][nt][3]);
            }
        }
    #undef ISSUE
}

// ---------------------------------------------------------------------------
// Causal flash attention: fp16 mma, register softmax (base-2), f16x2 exp,
// row-sum l accumulated by tensor core (P x ones), cp.async double-buffered.
// ---------------------------------------------------------------------------
#define LDFH 72
#define BUFFH (64 * LDFH)

__global__ __launch_bounds__(256)
void flash_f16(const __half* __restrict__ qkv, __half* __restrict__ out)
{
    extern __shared__ __half smf[];
    __half* Qstage = smf;

    const int qt = (int)gridDim.x - 1 - (int)blockIdx.x;
    const int h = blockIdx.y, b = blockIdx.z;
    const int tid = threadIdx.x;
    const int lane = tid & 31, w = tid >> 5;
    const int lr = lane >> 2, lc = lane & 3;
    const float NEG = -1e30f;
    const float qscale = 0.125f * 1.44269504089f;

    const int q0 = qt * 256;
    const size_t qrow0 = (size_t)(b * Tt + q0);
    const __half* qbase = qkv + qrow0 * C3 + h * HSs;

    {
        const __half* qr = qbase + (size_t)tid * C3;
        __half* qd = Qstage + tid * LDFH;
        #pragma unroll
        for (int c8 = 0; c8 < 64; c8 += 8) {
            uint4 u = *(const uint4*)(qr + c8);
            __half2* hp = (__half2*)&u;
            #pragma unroll
            for (int q = 0; q < 4; q++) {
                float2 f = __half22float2(hp[q]);
                hp[q] = __floats2half2_rn(f.x * qscale, f.y * qscale);
            }
            *(uint4*)(qd + c8) = u;
        }
    }
    __syncthreads();

    const int aRow = lane & 15, aKoff = (lane & 16) ? 8 : 0;
    uint32_t qf[2][4][4];
    #pragma unroll
    for (int mt = 0; mt < 2; mt++)
        #pragma unroll
        for (int ks = 0; ks < 4; ks++)
            ldsm4(qf[mt][ks], cvs(Qstage + (w * 32 + mt * 16 + aRow) * LDFH
                                     + ks * 16 + aKoff));
    __syncthreads();

    const int nIter = 4 * qt + 4;
    const __half* kvb = qkv + (size_t)(b * Tt) * C3 + Cc + h * HSs;

    #define ISSUEF(jb_, s_) do { \
        const __half* kb_ = kvb + (size_t)(jb_) * 64 * C3; \
        uint32_t kd_ = cvs(smf + (s_) * 2 * BUFFH); \
        uint32_t vd_ = kd_ + BUFFH * 2; \
        _Pragma("unroll") \
        for (int it = 0; it < 2; it++) { \
            int idx = tid + it * 256; \
            int r = idx >> 3, c8 = (idx & 7) << 3; \
            size_t go = (size_t)r * C3 + c8; \
            uint32_t so = (uint32_t)(r * LDFH + c8) * 2u; \
            cp16(kd_ + so, kb_ + go); \
            cp16(vd_ + so, kb_ + Cc + go); \
        } \
        cp_commit(); \
    } while (0)

    ISSUEF(0, 0);

    float accO[2][8][4];
    float lAcc[2][4];
    #pragma unroll
    for (int mt = 0; mt < 2; mt++) {
        #pragma unroll
        for (int j = 0; j < 8; j++)
            #pragma unroll
            for (int q = 0; q < 4; q++) accO[mt][j][q] = 0.f;
        #pragma unroll
        for (int q = 0; q < 4; q++) lAcc[mt][q] = 0.f;
    }
    float mrun[2][2] = {{NEG, NEG}, {NEG, NEG}};
    const uint32_t ONES2 = 0x3C003C00u;   // half2 {1,1}
    const uint32_t onesB[2] = {ONES2, ONES2};

    const int kRow = (lane & 7) + ((lane & 8) ? 8 : 0);
    const int kOff = (lane & 16) ? 8 : 0;

    for (int jb = 0; jb < nIter; jb++) {
        const int cur = jb & 1;
        __half* Ks = smf + cur * 2 * BUFFH;
        __half* Vs = Ks + BUFFH;

        __syncthreads();
        int nxt = jb + 1 < nIter ? jb + 1 : jb;
        ISSUEF(nxt, (jb + 1) & 1);
        cp_wait1();
        __syncthreads();

        // ---- S = Q x K^T ----
        float sAcc[2][8][4];
        #pragma unroll
        for (int mt = 0; mt < 2; mt++)
            #pragma unroll
            for (int j = 0; j < 8; j++)
                #pragma unroll
                for (int q = 0; q < 4; q++) sAcc[mt][j][q] = 0.f;

        #pragma unroll
        for (int ks = 0; ks < 4; ks++) {
            uint32_t kf[8][2];
            #pragma unroll
            for (int j2 = 0; j2 < 4; j2++) {
                uint32_t t[4];
                ldsm4(t, cvs(Ks + (j2 * 16 + kRow) * LDFH + ks * 16 + kOff));
                kf[2 * j2][0] = t[0]; kf[2 * j2][1] = t[2];
                kf[2 * j2 + 1][0] = t[1]; kf[2 * j2 + 1][1] = t[3];
            }
            #pragma unroll
            for (int nj = 0; nj < 8; nj++) {
                mma_f16(sAcc[0][nj], qf[0][ks], kf[nj]);
                mma_f16(sAcc[1][nj], qf[1][ks], kf[nj]);
            }
        }

        // ---- mask + online softmax (exp in f16x2, sum via ones-mma) ----
        uint32_t paf[2][4][4];
        #pragma unroll
        for (int mt = 0; mt < 2; mt++) {
            const int rowA = q0 + w * 32 + mt * 16 + lr;
            const int rowB = rowA + 8;
            if (jb * 64 + 63 > q0 + w * 32 + mt * 16) {
                #pragma unroll
                for (int nj = 0; nj < 8; nj++) {
                    int col = jb * 64 + nj * 8 + 2 * lc;
                    if (col > rowA)     sAcc[mt][nj][0] = NEG;
                    if (col + 1 > rowA) sAcc[mt][nj][1] = NEG;
                    if (col > rowB)     sAcc[mt][nj][2] = NEG;
                    if (col + 1 > rowB) sAcc[mt][nj][3] = NEG;
                }
            }

            float mxA = NEG, mxB = NEG;
            #pragma unroll
            for (int nj = 0; nj < 8; nj++) {
                mxA = fmaxf(mxA, fmaxf(sAcc[mt][nj][0], sAcc[mt][nj][1]));
                mxB = fmaxf(mxB, fmaxf(sAcc[mt][nj][2], sAcc[mt][nj][3]));
            }
            mxA = fmaxf(mxA, __shfl_xor_sync(0xffffffffu, mxA, 1));
            mxA = fmaxf(mxA, __shfl_xor_sync(0xffffffffu, mxA, 2));
            mxB = fmaxf(mxB, __shfl_xor_sync(0xffffffffu, mxB, 1));
            mxB = fmaxf(mxB, __shfl_xor_sync(0xffffffffu, mxB, 2));

            float mn0 = fmaxf(mrun[mt][0], mxA), mn1 = fmaxf(mrun[mt][1], mxB);
            float al0 = ex2(mrun[mt][0] - mn0), al1 = ex2(mrun[mt][1] - mn1);
            mrun[mt][0] = mn0; mrun[mt][1] = mn1;

            // P = 2^(S - mn), computed pairwise in f16x2 -> A-frag layout
            #pragma unroll
            for (int ks = 0; ks < 4; ks++) {
                paf[mt][ks][0] = ex2h2(pk(sAcc[mt][2 * ks][0] - mn0,
                                          sAcc[mt][2 * ks][1] - mn0));
                paf[mt][ks][1] = ex2h2(pk(sAcc[mt][2 * ks][2] - mn1,
                                          sAcc[mt][2 * ks][3] - mn1));
                paf[mt][ks][2] = ex2h2(pk(sAcc[mt][2 * ks + 1][0] - mn0,
                                          sAcc[mt][2 * ks + 1][1] - mn0));
                paf[mt][ks][3] = ex2h2(pk(sAcc[mt][2 * ks + 1][2] - mn1,
                                          sAcc[mt][2 * ks + 1][3] - mn1));
            }

            // rescale O and l
            #pragma unroll
            for (int nj = 0; nj < 8; nj++) {
                accO[mt][nj][0] *= al0; accO[mt][nj][1] *= al0;
                accO[mt][nj][2] *= al1; accO[mt][nj][3] *= al1;
            }
            lAcc[mt][0] *= al0; lAcc[mt][1] *= al0;
            lAcc[mt][2] *= al1; lAcc[mt][3] *= al1;

            // l += P x ones (every lane ends up holding its rows' sums)
            #pragma unroll
            for (int ks = 0; ks < 4; ks++)
                mma_f16(lAcc[mt], paf[mt][ks], onesB);
        }

        // ---- O += P x V ----
        #pragma unroll
        for (int ks = 0; ks < 4; ks++) {
            uint32_t vf[8][2];
            #pragma unroll
            for (int j2 = 0; j2 < 4; j2++) {
                uint32_t t[4];
                ldsm4t(t, cvs(Vs + (ks * 16 + kRow) * LDFH + j2 * 16 + kOff));
                vf[2 * j2][0] = t[0]; vf[2 * j2][1] = t[1];
                vf[2 * j2 + 1][0] = t[2]; vf[2 * j2 + 1][1] = t[3];
            }
            #pragma unroll
            for (int nj = 0; nj < 8; nj++) {
                mma_f16(accO[0][nj], paf[0][ks], vf[nj]);
                mma_f16(accO[1][nj], paf[1][ks], vf[nj]);
            }
        }
    }

    cp_wait0();

    __half* obase = out + qrow0 * Cc + h * HSs;
    #pragma unroll
    for (int mt = 0; mt < 2; mt++) {
        int r0 = w * 32 + mt * 16 + lr;
        float rl0 = 1.f / lAcc[mt][0], rl1 = 1.f / lAcc[mt][2];
        #pragma unroll
        for (int nj = 0; nj < 8; nj++) {
            int col = nj * 8 + 2 * lc;
            *(__half2*)(obase + (size_t)r0 * Cc + col) =
                __floats2half2_rn(accO[mt][nj][0] * rl0, accO[mt][nj][1] * rl0);
            *(__half2*)(obase + (size_t)(r0 + 8) * Cc + col) =
                __floats2half2_rn(accO[mt][nj][2] * rl1, accO[mt][nj][3] * rl1);
        }
    }
    #undef ISSUEF
}

// ---------------------------------------------------------------------------
extern "C" void kernel_launch(void* const* d_in, const int* in_sizes, int n_in,
                              void* d_out, int out_size)
{
    const float* x      = (const float*)d_in[0];
    const float* w_attn = (const float*)d_in[1];
    const float* w_proj = (const float*)d_in[2];
    float* out = (float*)d_out;

    __half *qkv, *att, *xh, *wa, *wp;
    cudaGetSymbolAddress((void**)&qkv, g_qkv);
    cudaGetSymbolAddress((void**)&att, g_att);
    cudaGetSymbolAddress((void**)&xh, g_xh);
    cudaGetSymbolAddress((void**)&wa, g_wa);
    cudaGetSymbolAddress((void**)&wp, g_wp);

    const int GEMM_SMEM = GEMM_SMEM_H * sizeof(__half);     // 54272 B
    const int FLASH_SMEM = 4 * BUFFH * sizeof(__half);      // 36864 B
    cudaFuncSetAttribute(gemm_h16<__half>,
                         cudaFuncAttributeMaxDynamicSharedMemorySize, GEMM_SMEM);
    cudaFuncSetAttribute(gemm_h16<float>,
                         cudaFuncAttributeMaxDynamicSharedMemorySize, GEMM_SMEM);
    cudaFuncSetAttribute(flash_f16,
                         cudaFuncAttributeMaxDynamicSharedMemorySize, FLASH_SMEM);

    // 0) fp32 -> fp16 conversions
    {
        int n4;
        n4 = BT * Cc / 4;  f2h<<<(n4 + 255) / 256, 256>>>(x, xh, n4);
        n4 = Cc * C3 / 4;  f2h<<<(n4 + 255) / 256, 256>>>(w_attn, wa, n4);
        n4 = Cc * Cc / 4;  f2h<<<(n4 + 255) / 256, 256>>>(w_proj, wp, n4);
    }
    // 1) QKV projection (all-half, 128x256 tiles)
    gemm_h16<__half><<<dim3(C3 / 256, BT / 128), 256, GEMM_SMEM>>>(
        xh, wa, qkv, BT, C3, Cc);
    // 2) Causal flash attention
    flash_f16<<<dim3(Tt / 256, NHh, Bb), 256, FLASH_SMEM>>>(qkv, att);
    // 3) Output projection (half in, float out)
    gemm_h16<float><<<dim3(Cc / 256, BT / 128), 256, GEMM_SMEM>>>(
        att, wp, out, BT, Cc, Cc);
}

// round 11
// speedup vs baseline: 1.0264x; 1.0264x over previous
#include <cuda_runtime.h>
#include <cuda_fp16.h>
#include <math.h>
#include <stdint.h>

#define Bb 2
#define Tt 4096
#define Cc 768
#define NHh 12
#define HSs 64
#define BT (Bb*Tt)
#define C3 (3*Cc)

__device__ __half g_qkv[(size_t)BT * C3];   // [B*T, 3C] fp16
__device__ __half g_att[(size_t)BT * Cc];   // [B*T, C]  fp16
__device__ __half g_xh [(size_t)BT * Cc];   // x in fp16
__device__ __half g_wa [(size_t)Cc * C3];   // w_attn fp16
__device__ __half g_wp [(size_t)Cc * Cc];   // w_proj fp16

__device__ __forceinline__ uint32_t h2u(__half2 h) {
    return *reinterpret_cast<uint32_t*>(&h);
}
__device__ __forceinline__ uint32_t pk(float a, float b) {
    __half2 h = __floats2half2_rn(a, b);
    return h2u(h);
}
__device__ __forceinline__ float ex2(float x) {
    float r;
    asm("ex2.approx.ftz.f32 %0, %1;" : "=f"(r) : "f"(x));
    return r;
}
__device__ __forceinline__ uint32_t ex2h2(uint32_t x) {
    uint32_t r;
    asm("ex2.approx.f16x2 %0, %1;" : "=r"(r) : "r"(x));
    return r;
}
__device__ __forceinline__ void cp16(uint32_t dst, const void* src) {
    asm volatile("cp.async.cg.shared.global [%0], [%1], 16;" :: "r"(dst), "l"(src));
}
__device__ __forceinline__ void cp_commit() { asm volatile("cp.async.commit_group;"); }
__device__ __forceinline__ void cp_wait1()  { asm volatile("cp.async.wait_group 1;"); }
__device__ __forceinline__ void cp_wait0()  { asm volatile("cp.async.wait_group 0;"); }

__device__ __forceinline__ void mma_f16(float c[4], const uint32_t a[4], const uint32_t b[2]) {
    asm volatile(
        "mma.sync.aligned.m16n8k16.row.col.f32.f16.f16.f32 "
        "{%0,%1,%2,%3},{%4,%5,%6,%7},{%8,%9},{%0,%1,%2,%3};"
        : "+f"(c[0]), "+f"(c[1]), "+f"(c[2]), "+f"(c[3])
        : "r"(a[0]), "r"(a[1]), "r"(a[2]), "r"(a[3]), "r"(b[0]), "r"(b[1]));
}
__device__ __forceinline__ void ldsm4(uint32_t r[4], uint32_t saddr) {
    asm volatile("ldmatrix.sync.aligned.m8n8.x4.shared.b16 {%0,%1,%2,%3}, [%4];"
                 : "=r"(r[0]), "=r"(r[1]), "=r"(r[2]), "=r"(r[3]) : "r"(saddr));
}
__device__ __forceinline__ void ldsm4t(uint32_t r[4], uint32_t saddr) {
    asm volatile("ldmatrix.sync.aligned.m8n8.x4.trans.shared.b16 {%0,%1,%2,%3}, [%4];"
                 : "=r"(r[0]), "=r"(r[1]), "=r"(r[2]), "=r"(r[3]) : "r"(saddr));
}
__device__ __forceinline__ uint32_t cvs(const void* p) {
    return (uint32_t)__cvta_generic_to_shared(p);
}

// ---------------------------------------------------------------------------
// fp32 -> fp16 bulk convert
// ---------------------------------------------------------------------------
__global__ void f2h(const float* __restrict__ src, __half* __restrict__ dst, int n4)
{
    int i = blockIdx.x * blockDim.x + threadIdx.x;
    if (i < n4) {
        float4 v = *(const float4*)(src + (size_t)i * 4);
        uint2 u;
        u.x = pk(v.x, v.y);
        u.y = pk(v.z, v.w);
        *(uint2*)(dst + (size_t)i * 4) = u;
    }
}

// ---------------------------------------------------------------------------
// All-half GEMM (R9, verbatim): CTA 128x256, 8 warps, warp 64x64, kc=32,
// cp.async double-buffered, LDSM+HMMA hot loop.
// ---------------------------------------------------------------------------
#define LDAH 40
#define LDBH 264
#define GA_H(s) ((s) * 128 * LDAH)
#define GB_H(s) (2 * 128 * LDAH + (s) * 32 * LDBH)
#define GEMM_SMEM_H (2 * 128 * LDAH + 2 * 32 * LDBH)

template <typename TC>
__global__ __launch_bounds__(256)
void gemm_h16(const __half* __restrict__ A, const __half* __restrict__ B,
              TC* __restrict__ C, int M, int N, int K)
{
    extern __shared__ __half smh[];

    const int tid = threadIdx.x;
    const int lane = tid & 31, wid = tid >> 5;
    const int warpM = wid >> 2, warpN = wid & 3;
    const int lr = lane >> 2, lc = lane & 3;
    const int brow = blockIdx.y << 7, bcol = blockIdx.x << 8;

    const __half* Ab = A + (size_t)brow * K;
    const __half* Bbp = B + bcol;

    float acc[4][8][4];
    #pragma unroll
    for (int i = 0; i < 4; i++)
        #pragma unroll
        for (int j = 0; j < 8; j++)
            #pragma unroll
            for (int q = 0; q < 4; q++) acc[i][j][q] = 0.f;

    #define ISSUE(kt, s) do { \
        uint32_t as_ = cvs(smh + GA_H(s)); \
        uint32_t bs_ = cvs(smh + GB_H(s)); \
        _Pragma("unroll") \
        for (int it = 0; it < 2; it++) { \
            int idx = tid + it * 256; \
            int r = idx >> 2, c8 = (idx & 3) << 3; \
            cp16(as_ + (uint32_t)(r * LDAH + c8) * 2u, \
                 Ab + (size_t)r * K + (kt) * 32 + c8); \
        } \
        _Pragma("unroll") \
        for (int it = 0; it < 4; it++) { \
            int idx = tid + it * 256; \
            int r = idx >> 5, c8 = (idx & 31) << 3; \
            cp16(bs_ + (uint32_t)(r * LDBH + c8) * 2u, \
                 Bbp + (size_t)((kt) * 32 + r) * N + c8); \
        } \
        cp_commit(); \
    } while (0)

    const int NT = K >> 5;
    ISSUE(0, 0);

    const int aRow = lane & 15, aKoff = (lane & 16) ? 8 : 0;
    const int bRow = (lane & 7) + ((lane & 8) ? 8 : 0);
    const int bNoff = (lane & 16) ? 8 : 0;

    for (int kt = 0; kt < NT; kt++) {
        const int cur = kt & 1;
        if (kt + 1 < NT) { ISSUE(kt + 1, (kt + 1) & 1); cp_wait1(); }
        else cp_wait0();
        __syncthreads();

        const __half* Ac = smh + GA_H(cur);
        const __half* Bc = smh + GB_H(cur);
        #pragma unroll
        for (int ks = 0; ks < 2; ks++) {
            uint32_t af[4][4];
            #pragma unroll
            for (int mt = 0; mt < 4; mt++)
                ldsm4(af[mt], cvs(Ac + (warpM * 64 + mt * 16 + aRow) * LDAH
                                     + ks * 16 + aKoff));
            uint32_t bf[8][2];
            #pragma unroll
            for (int j2 = 0; j2 < 4; j2++) {
                uint32_t t[4];
                ldsm4t(t, cvs(Bc + (ks * 16 + bRow) * LDBH
                                 + warpN * 64 + j2 * 16 + bNoff));
                bf[2 * j2][0] = t[0]; bf[2 * j2][1] = t[1];
                bf[2 * j2 + 1][0] = t[2]; bf[2 * j2 + 1][1] = t[3];
            }
            #pragma unroll
            for (int mt = 0; mt < 4; mt++)
                #pragma unroll
                for (int nt = 0; nt < 8; nt++)
                    mma_f16(acc[mt][nt], af[mt], bf[nt]);
        }
        __syncthreads();
    }

    #pragma unroll
    for (int mt = 0; mt < 4; mt++)
        #pragma unroll
        for (int nt = 0; nt < 8; nt++) {
            int row = brow + warpM * 64 + mt * 16 + lr;
            int col = bcol + warpN * 64 + nt * 8 + 2 * lc;
            if constexpr (sizeof(TC) == 2) {
                *(__half2*)&C[(size_t)row * N + col] =
                    __floats2half2_rn(acc[mt][nt][0], acc[mt][nt][1]);
                *(__half2*)&C[(size_t)(row + 8) * N + col] =
                    __floats2half2_rn(acc[mt][nt][2], acc[mt][nt][3]);
            } else {
                *(float2*)&C[(size_t)row * N + col] =
                    make_float2(acc[mt][nt][0], acc[mt][nt][1]);
                *(float2*)&C[(size_t)(row + 8) * N + col] =
                    make_float2(acc[mt][nt][2], acc[mt][nt][3]);
            }
        }
    #undef ISSUE
}

// ---------------------------------------------------------------------------
// Causal flash attention: fp16 mma, register softmax (base-2), f16x2 exp,
// l via ones-mma. 128-key K/V stages (one cp.async wait + 2 syncs per 128
// keys), processed as two 64-key sub-steps sharing registers.
// ---------------------------------------------------------------------------
#define LDFH 72
#define KBUF (128 * LDFH)       // one 128x64 K or V tile (halfs)

__global__ __launch_bounds__(256)
void flash_f16(const __half* __restrict__ qkv, __half* __restrict__ out)
{
    extern __shared__ __half smf[];
    __half* Qstage = smf;

    const int qt = (int)gridDim.x - 1 - (int)blockIdx.x;
    const int h = blockIdx.y, b = blockIdx.z;
    const int tid = threadIdx.x;
    const int lane = tid & 31, w = tid >> 5;
    const int lr = lane >> 2, lc = lane & 3;
    const float NEG = -1e30f;
    const float qscale = 0.125f * 1.44269504089f;

    const int q0 = qt * 256;
    const size_t qrow0 = (size_t)(b * Tt + q0);
    const __half* qbase = qkv + qrow0 * C3 + h * HSs;

    {
        const __half* qr = qbase + (size_t)tid * C3;
        __half* qd = Qstage + tid * LDFH;
        #pragma unroll
        for (int c8 = 0; c8 < 64; c8 += 8) {
            uint4 u = *(const uint4*)(qr + c8);
            __half2* hp = (__half2*)&u;
            #pragma unroll
            for (int q = 0; q < 4; q++) {
                float2 f = __half22float2(hp[q]);
                hp[q] = __floats2half2_rn(f.x * qscale, f.y * qscale);
            }
            *(uint4*)(qd + c8) = u;
        }
    }
    __syncthreads();

    const int aRow = lane & 15, aKoff = (lane & 16) ? 8 : 0;
    uint32_t qf[2][4][4];
    #pragma unroll
    for (int mt = 0; mt < 2; mt++)
        #pragma unroll
        for (int ks = 0; ks < 4; ks++)
            ldsm4(qf[mt][ks], cvs(Qstage + (w * 32 + mt * 16 + aRow) * LDFH
                                     + ks * 16 + aKoff));
    __syncthreads();

    const int nIter = 2 * qt + 2;            // 128-key tiles
    const __half* kvb = qkv + (size_t)(b * Tt) * C3 + Cc + h * HSs;

    // one stage = K tile (128xLDFH) + V tile (128xLDFH); 8 cp16/thread
    #define ISSUEF(jb_, s_) do { \
        const __half* kb_ = kvb + (size_t)(jb_) * 128 * C3; \
        uint32_t kd_ = cvs(smf + (s_) * 2 * KBUF); \
        uint32_t vd_ = kd_ + KBUF * 2; \
        _Pragma("unroll") \
        for (int it = 0; it < 4; it++) { \
            int idx = tid + it * 256; \
            int r = idx >> 3, c8 = (idx & 7) << 3; \
            size_t go = (size_t)r * C3 + c8; \
            uint32_t so = (uint32_t)(r * LDFH + c8) * 2u; \
            cp16(kd_ + so, kb_ + go); \
            cp16(vd_ + so, kb_ + Cc + go); \
        } \
        cp_commit(); \
    } while (0)

    ISSUEF(0, 0);

    float accO[2][8][4];
    float lAcc[2][4];
    #pragma unroll
    for (int mt = 0; mt < 2; mt++) {
        #pragma unroll
        for (int j = 0; j < 8; j++)
            #pragma unroll
            for (int q = 0; q < 4; q++) accO[mt][j][q] = 0.f;
        #pragma unroll
        for (int q = 0; q < 4; q++) lAcc[mt][q] = 0.f;
    }
    float mrun[2][2] = {{NEG, NEG}, {NEG, NEG}};
    const uint32_t ONES2 = 0x3C003C00u;
    const uint32_t onesB[2] = {ONES2, ONES2};

    const int kRow = (lane & 7) + ((lane & 8) ? 8 : 0);
    const int kOff = (lane & 16) ? 8 : 0;

    for (int jb = 0; jb < nIter; jb++) {
        const int cur = jb & 1;
        __half* Kt = smf + cur * 2 * KBUF;
        __half* Vt = Kt + KBUF;

        __syncthreads();
        int nxt = jb + 1 < nIter ? jb + 1 : jb;
        ISSUEF(nxt, (jb + 1) & 1);
        cp_wait1();
        __syncthreads();

        #pragma unroll
        for (int sub = 0; sub < 2; sub++) {
            const int kb64 = jb * 2 + sub;           // 64-key step index
            __half* Ks = Kt + sub * 64 * LDFH;
            __half* Vs = Vt + sub * 64 * LDFH;

            // ---- S = Q x K^T ----
            float sAcc[2][8][4];
            #pragma unroll
            for (int mt = 0; mt < 2; mt++)
                #pragma unroll
                for (int j = 0; j < 8; j++)
                    #pragma unroll
                    for (int q = 0; q < 4; q++) sAcc[mt][j][q] = 0.f;

            #pragma unroll
            for (int ks = 0; ks < 4; ks++) {
                uint32_t kf[8][2];
                #pragma unroll
                for (int j2 = 0; j2 < 4; j2++) {
                    uint32_t t[4];
                    ldsm4(t, cvs(Ks + (j2 * 16 + kRow) * LDFH + ks * 16 + kOff));
                    kf[2 * j2][0] = t[0]; kf[2 * j2][1] = t[2];
                    kf[2 * j2 + 1][0] = t[1]; kf[2 * j2 + 1][1] = t[3];
                }
                #pragma unroll
                for (int nj = 0; nj < 8; nj++) {
                    mma_f16(sAcc[0][nj], qf[0][ks], kf[nj]);
                    mma_f16(sAcc[1][nj], qf[1][ks], kf[nj]);
                }
            }

            // ---- mask + online softmax ----
            uint32_t paf[2][4][4];
            #pragma unroll
            for (int mt = 0; mt < 2; mt++) {
                const int rowA = q0 + w * 32 + mt * 16 + lr;
                const int rowB = rowA + 8;
                if (kb64 * 64 + 63 > q0 + w * 32 + mt * 16) {
                    #pragma unroll
                    for (int nj = 0; nj < 8; nj++) {
                        int col = kb64 * 64 + nj * 8 + 2 * lc;
                        if (col > rowA)     sAcc[mt][nj][0] = NEG;
                        if (col + 1 > rowA) sAcc[mt][nj][1] = NEG;
                        if (col > rowB)     sAcc[mt][nj][2] = NEG;
                        if (col + 1 > rowB) sAcc[mt][nj][3] = NEG;
                    }
                }

                float mxA = NEG, mxB = NEG;
                #pragma unroll
                for (int nj = 0; nj < 8; nj++) {
                    mxA = fmaxf(mxA, fmaxf(sAcc[mt][nj][0], sAcc[mt][nj][1]));
                    mxB = fmaxf(mxB, fmaxf(sAcc[mt][nj][2], sAcc[mt][nj][3]));
                }
                mxA = fmaxf(mxA, __shfl_xor_sync(0xffffffffu, mxA, 1));
                mxA = fmaxf(mxA, __shfl_xor_sync(0xffffffffu, mxA, 2));
                mxB = fmaxf(mxB, __shfl_xor_sync(0xffffffffu, mxB, 1));
                mxB = fmaxf(mxB, __shfl_xor_sync(0xffffffffu, mxB, 2));

                float mn0 = fmaxf(mrun[mt][0], mxA), mn1 = fmaxf(mrun[mt][1], mxB);
                float al0 = ex2(mrun[mt][0] - mn0), al1 = ex2(mrun[mt][1] - mn1);
                mrun[mt][0] = mn0; mrun[mt][1] = mn1;

                #pragma unroll
                for (int ks = 0; ks < 4; ks++) {
                    paf[mt][ks][0] = ex2h2(pk(sAcc[mt][2 * ks][0] - mn0,
                                              sAcc[mt][2 * ks][1] - mn0));
                    paf[mt][ks][1] = ex2h2(pk(sAcc[mt][2 * ks][2] - mn1,
                                              sAcc[mt][2 * ks][3] - mn1));
                    paf[mt][ks][2] = ex2h2(pk(sAcc[mt][2 * ks + 1][0] - mn0,
                                              sAcc[mt][2 * ks + 1][1] - mn0));
                    paf[mt][ks][3] = ex2h2(pk(sAcc[mt][2 * ks + 1][2] - mn1,
                                              sAcc[mt][2 * ks + 1][3] - mn1));
                }

                #pragma unroll
                for (int nj = 0; nj < 8; nj++) {
                    accO[mt][nj][0] *= al0; accO[mt][nj][1] *= al0;
                    accO[mt][nj][2] *= al1; accO[mt][nj][3] *= al1;
                }
                lAcc[mt][0] *= al0; lAcc[mt][1] *= al0;
                lAcc[mt][2] *= al1; lAcc[mt][3] *= al1;

                #pragma unroll
                for (int ks = 0; ks < 4; ks++)
                    mma_f16(lAcc[mt], paf[mt][ks], onesB);
            }

            // ---- O += P x V ----
            #pragma unroll
            for (int ks = 0; ks < 4; ks++) {
                uint32_t vf[8][2];
                #pragma unroll
                for (int j2 = 0; j2 < 4; j2++) {
                    uint32_t t[4];
                    ldsm4t(t, cvs(Vs + (ks * 16 + kRow) * LDFH + j2 * 16 + kOff));
                    vf[2 * j2][0] = t[0]; vf[2 * j2][1] = t[1];
                    vf[2 * j2 + 1][0] = t[2]; vf[2 * j2 + 1][1] = t[3];
                }
                #pragma unroll
                for (int nj = 0; nj < 8; nj++) {
                    mma_f16(accO[0][nj], paf[0][ks], vf[nj]);
                    mma_f16(accO[1][nj], paf[1][ks], vf[nj]);
                }
            }
        }
    }

    cp_wait0();

    __half* obase = out + qrow0 * Cc + h * HSs;
    #pragma unroll
    for (int mt = 0; mt < 2; mt++) {
        int r0 = w * 32 + mt * 16 + lr;
        float rl0 = 1.f / lAcc[mt][0], rl1 = 1.f / lAcc[mt][2];
        #pragma unroll
        for (int nj = 0; nj < 8; nj++) {
            int col = nj * 8 + 2 * lc;
            *(__half2*)(obase + (size_t)r0 * Cc + col) =
                __floats2half2_rn(accO[mt][nj][0] * rl0, accO[mt][nj][1] * rl0);
            *(__half2*)(obase + (size_t)(r0 + 8) * Cc + col) =
                __floats2half2_rn(accO[mt][nj][2] * rl1, accO[mt][nj][3] * rl1);
        }
    }
    #undef ISSUEF
}

// ---------------------------------------------------------------------------
extern "C" void kernel_launch(void* const* d_in, const int* in_sizes, int n_in,
                              void* d_out, int out_size)
{
    const float* x      = (const float*)d_in[0];
    const float* w_attn = (const float*)d_in[1];
    const float* w_proj = (const float*)d_in[2];
    float* out = (float*)d_out;

    __half *qkv, *att, *xh, *wa, *wp;
    cudaGetSymbolAddress((void**)&qkv, g_qkv);
    cudaGetSymbolAddress((void**)&att, g_att);
    cudaGetSymbolAddress((void**)&xh, g_xh);
    cudaGetSymbolAddress((void**)&wa, g_wa);
    cudaGetSymbolAddress((void**)&wp, g_wp);

    const int GEMM_SMEM = GEMM_SMEM_H * sizeof(__half);     // 54272 B
    const int FLASH_SMEM = 4 * KBUF * sizeof(__half);       // 73728 B
    cudaFuncSetAttribute(gemm_h16<__half>,
                         cudaFuncAttributeMaxDynamicSharedMemorySize, GEMM_SMEM);
    cudaFuncSetAttribute(gemm_h16<float>,
                         cudaFuncAttributeMaxDynamicSharedMemorySize, GEMM_SMEM);
    cudaFuncSetAttribute(flash_f16,
                         cudaFuncAttributeMaxDynamicSharedMemorySize, FLASH_SMEM);

    // 0) fp32 -> fp16 conversions
    {
        int n4;
        n4 = BT * Cc / 4;  f2h<<<(n4 + 255) / 256, 256>>>(x, xh, n4);
        n4 = Cc * C3 / 4;  f2h<<<(n4 + 255) / 256, 256>>>(w_attn, wa, n4);
        n4 = Cc * Cc / 4;  f2h<<<(n4 + 255) / 256, 256>>>(w_proj, wp, n4);
    }
    // 1) QKV projection (all-half, 128x256 tiles)
    gemm_h16<__half><<<dim3(C3 / 256, BT / 128), 256, GEMM_SMEM>>>(
        xh, wa, qkv, BT, C3, Cc);
    // 2) Causal flash attention (128-key stages)
    flash_f16<<<dim3(Tt / 256, NHh, Bb), 256, FLASH_SMEM>>>(qkv, att);
    // 3) Output projection (half in, float out)
    gemm_h16<float><<<dim3(Cc / 256, BT / 128), 256, GEMM_SMEM>>>(
        att, wp, out, BT, Cc, Cc);
}